// round 16
// baseline (speedup 1.0000x reference)
#include <cuda_runtime.h>
#include <cuda_bf16.h>
#include <cstdint>
#include <math.h>

#define NB 16
#define LL 1000
#define DD 1024
#define LP 1024                 // padded per-batch rows
#define MM (NB*LL)              // 16000
#define MP (NB*LP)              // 16384 padded

typedef __nv_bfloat16 bf16;
typedef __nv_bfloat162 bf162;

#if defined(__CUDA_ARCH__) && (defined(__CUDA_ARCH_FEAT_SM103_ALL) || defined(__CUDA_ARCH_FEAT_SM100_ALL))
#define TC_OK 1
#endif

// ---------------- scratch: ALL GEMM operands live in tiled-swizzled layout ----------------
// Tiled layout: blocks of 256 rows x 32 cols (16KB, SW64-swizzled, ready for MMA).
// block id = (row>>8)*KC + (col>>5).
__device__ __align__(128) bf16  g_xh  [NB*LP*DD];
__device__ __align__(128) bf16  g_xl  [NB*LP*DD];
__device__ __align__(128) bf16  g_xuh [NB*LP*DD];
__device__ __align__(128) bf16  g_xul [NB*LP*DD];
__device__ __align__(128) bf16  g_qkh [NB*LP*2*DD];
__device__ __align__(128) bf16  g_qkl [NB*LP*2*DD];
__device__ __align__(128) bf16  g_quhh[NB*LP*DD];
__device__ __align__(128) bf16  g_quhl[NB*LP*DD];
__device__ __align__(128) bf16  g_vth [NB*DD*LP];
__device__ __align__(128) bf16  g_vtl [NB*DD*LP];
__device__ float g_s   [2*NB*LP*LL];
__device__ __align__(128) bf16  g_ph  [2*NB*LP*LP];
__device__ __align__(128) bf16  g_pl  [2*NB*LP*LP];
__device__ float g_o   [2*NB*LP*DD];
__device__ __align__(128) bf16  g_ynh [NB*LP*DD];
__device__ __align__(128) bf16  g_ynl [NB*LP*DD];
__device__ __align__(128) bf16  g_wh  [5*DD*DD];
__device__ __align__(128) bf16  g_wl  [5*DD*DD];

// ================= helpers =================
__device__ __forceinline__ uint32_t smem_u32(const void* p) {
    uint32_t a;
    asm("{ .reg .u64 t; cvta.to.shared.u64 t, %1; cvt.u32.u64 %0, t; }" : "=r"(a) : "l"(p));
    return a;
}

__device__ __forceinline__ void bsplit(float v, bf16& h, bf16& l) {
    h = __float2bfloat16_rn(v);
    l = __float2bfloat16_rn(v - __bfloat162float(h));
}

#define SWZ64(o) ((o) ^ (((o) >> 3) & 0x30))

// element offset of (row, col) in a tiled buffer with KC col-chunks
__device__ __forceinline__ long long toff(int row, int col, int KC) {
    int rb = row >> 8, r = row & 255;
    int kc = col >> 5, cc = col & 31;
    long long boff = ((long long)(rb * KC + kc)) << 13;   // 8192 elems / block
    uint32_t w = SWZ64((uint32_t)(r * 64 + (cc >> 3) * 16)) + (uint32_t)(cc & 7) * 2;
    return boff + (w >> 1);
}

#ifdef TC_OK
__device__ __forceinline__ bool elect1() {
    uint32_t p;
    asm volatile("{\n\t.reg .pred p;\n\telect.sync _|p, 0xFFFFFFFF;\n\tselp.b32 %0,1,0,p;\n\t}" : "=r"(p));
    return p != 0;
}

__device__ __forceinline__ uint32_t ctarank() {
    uint32_t r;
    asm("mov.u32 %0, %%cluster_ctarank;" : "=r"(r));
    return r;
}

#define TC_ALLOC_CG2(smaddr, n) \
    asm volatile("tcgen05.alloc.cta_group::2.sync.aligned.shared::cta.b32 [%0], %1;" :: "r"(smaddr), "r"(n) : "memory")
#define TC_RELINQ_CG2() \
    asm volatile("tcgen05.relinquish_alloc_permit.cta_group::2.sync.aligned;")
#define TC_DEALLOC_CG2(t, n) \
    asm volatile("tcgen05.dealloc.cta_group::2.sync.aligned.b32 %0, %1;" :: "r"(t), "r"(n))
#define TC_COMMIT_MC(mbar, mask) \
    asm volatile("tcgen05.commit.cta_group::2.mbarrier::arrive::one.shared::cluster.multicast::cluster.b64 [%0], %1;" \
        :: "r"(mbar), "h"((uint16_t)(mask)) : "memory")
#define TC_FENCE_AFTER() \
    asm volatile("tcgen05.fence::after_thread_sync;" ::: "memory")
#define TC_WAIT_LD() \
    asm volatile("tcgen05.wait::ld.sync.aligned;" ::: "memory")
#define MBAR_INIT(a, c) \
    asm volatile("mbarrier.init.shared.b64 [%0], %1;" :: "r"(a), "r"(c) : "memory")
#define MBAR_INVAL(a) \
    asm volatile("mbarrier.inval.shared.b64 [%0];" :: "r"(a) : "memory")
#define MBAR_EXPECT_TX(a, n) \
    asm volatile("mbarrier.arrive.expect_tx.shared.b64 _, [%0], %1;" :: "r"(a), "r"(n) : "memory")
#define MBWAIT(addr, ph) do { \
    asm volatile("{\n\t.reg .pred P1;\n\tWL%=:\n\t" \
        "mbarrier.try_wait.parity.acquire.cta.shared::cta.b64 P1, [%0], %1, 0x989680;\n\t" \
        "@P1 bra.uni WD%=;\n\tbra.uni WL%=;\n\tWD%=:\n\t}" \
        :: "r"(addr), "r"(ph) : "memory"); } while (0)

// arrive on the same-offset mbarrier in cluster CTA rank 0
#define ARRIVE_RANK0(addr) \
    asm volatile("{\n\t.reg .b32 ra;\n\t" \
        "mapa.shared::cluster.u32 ra, %0, %1;\n\t" \
        "mbarrier.arrive.shared::cluster.b64 _, [ra];\n\t}" \
        :: "r"(addr), "r"(0u) : "memory")

#define CLUSTER_SYNC() do { \
    asm volatile("barrier.cluster.arrive.aligned;" ::: "memory"); \
    asm volatile("barrier.cluster.wait.aligned;" ::: "memory"); } while (0)

#define BULK(dst, src, n, mbar) \
    asm volatile("cp.async.bulk.shared::cluster.global.mbarrier::complete_tx::bytes [%0], [%1], %2, [%3];" \
        :: "r"(dst), "l"(src), "r"(n), "r"(mbar) : "memory")

__device__ __forceinline__ void mma_bf16_cg2(uint32_t d, uint64_t ad, uint64_t bd, uint32_t idesc, uint32_t en) {
    uint32_t z = 0;
    asm volatile("{\n\t.reg .pred p;\n\tsetp.ne.u32 p, %5, 0;\n\t"
                 "tcgen05.mma.cta_group::2.kind::f16 [%0], %1, %2, %3, {%4, %4, %4, %4, %4, %4, %4, %4}, p;\n\t}"
                 :: "r"(d), "l"(ad), "l"(bd), "r"(idesc), "r"(z), "r"(en) : "memory");
}

#define LDTM_X32(r, a) \
    asm volatile("tcgen05.ld.sync.aligned.32x32b.x32.b32 " \
        "{%0, %1, %2, %3, %4, %5, %6, %7, %8, %9, %10, %11, %12, %13, %14, %15, " \
        " %16, %17, %18, %19, %20, %21, %22, %23, %24, %25, %26, %27, %28, %29, %30, %31}, [%32];" \
        : "=r"((r)[0]),  "=r"((r)[1]),  "=r"((r)[2]),  "=r"((r)[3]), \
          "=r"((r)[4]),  "=r"((r)[5]),  "=r"((r)[6]),  "=r"((r)[7]), \
          "=r"((r)[8]),  "=r"((r)[9]),  "=r"((r)[10]), "=r"((r)[11]), \
          "=r"((r)[12]), "=r"((r)[13]), "=r"((r)[14]), "=r"((r)[15]), \
          "=r"((r)[16]), "=r"((r)[17]), "=r"((r)[18]), "=r"((r)[19]), \
          "=r"((r)[20]), "=r"((r)[21]), "=r"((r)[22]), "=r"((r)[23]), \
          "=r"((r)[24]), "=r"((r)[25]), "=r"((r)[26]), "=r"((r)[27]), \
          "=r"((r)[28]), "=r"((r)[29]), "=r"((r)[30]), "=r"((r)[31]) \
        : "r"(a))

// SW64 descriptor: layout=4, version=1, SBO=32, LBO=1 (K-major, 64B rows)
__device__ __forceinline__ uint64_t sdesc64(uint32_t addr) {
    const uint64_t base = (uint64_t(4) << 61) | (uint64_t(1) << 46) |
                          (uint64_t(32) << 32) | (uint64_t(1) << 16);
    return base | ((uint64_t)(addr >> 4) & 0x3FFF);
}
#endif // TC_OK

// ================= cg2 bf16x2 GEMM: 256x256 pair tile, bulk loads, 6-stage =================
// C[M,Nn] = A[M,K] @ B[Nn,K]^T, bf16 (hi, lo) TILED operands.
// Per CTA per chunk: A-half 128 rows + B-half 128 rows (8KB x 4 planes = 32KB).
// Leader (rank 0) issues 6 cg2 MMAs/chunk (M=256, N=256); follower relays bulk
// completion to leader's count-2 full barrier; multicast commit recycles stages.
#define ST 6
#define STAGE_BYTES 32768
#define NTHR 512
static const int SMEM_DYN = ST * STAGE_BYTES + 1024;

template<bool CSKIP, bool CKLIM, bool BIAS, bool SPLITOUT, bool BATCHROW, bool DUAL>
__global__ __launch_bounds__(NTHR, 1) __cluster_dims__(2, 1, 1)
void tgemm(const bf16* __restrict__ Ah, const bf16* __restrict__ Al,
           const bf16* __restrict__ A2h, const bf16* __restrict__ A2l,
           const bf16* __restrict__ Bh, const bf16* __restrict__ Bl,
           float* __restrict__ C, bf16* __restrict__ Ch, bf16* __restrict__ Cl,
           const float* __restrict__ bias,
           int M, int Nn, int K, int kca, int kca2, int kcb, int ldc, int kcOffB,
           long long sA, long long sA2, long long sB, long long sC)
{
#ifdef TC_OK
    extern __shared__ char dsm[];
    __shared__ uint32_t s_tmem;
    __shared__ __align__(8) unsigned long long s_full[ST];   // leader: count 2 + tx; follower: count 1 + tx
    __shared__ __align__(8) unsigned long long s_done[ST];

    int m0 = blockIdx.y * 256, n0 = (blockIdx.x >> 1) * 256;
    if (CSKIP && n0 > m0 + 255) return;          // whole pair exits together

    uint32_t rank = ctarank();

    long long bz = blockIdx.z;
    if (DUAL && bz >= NB) {
        Ah = A2h + (bz - NB) * sA2;
        Al = A2l + (bz - NB) * sA2;
        kca = kca2;
    } else {
        Ah += bz * sA; Al += bz * sA;
    }
    long long bzb = bz % NB;
    Bh += bzb * sB; Bl += bzb * sB;
    C += bz * sC; Ch += bz * sC; Cl += bz * sC;

    uint32_t sb_raw = smem_u32(dsm);
    uint32_t sbase  = (sb_raw + 1023u) & ~1023u;

    int tid = threadIdx.x;
    int wid = tid >> 5;
    int lid = tid & 31;

    if (wid == 0) { TC_ALLOC_CG2(smem_u32(&s_tmem), 256); TC_RELINQ_CG2(); }
    if (tid < ST) {
        MBAR_INIT(smem_u32(&s_full[tid]), rank == 0 ? 2 : 1);
        MBAR_INIT(smem_u32(&s_done[tid]), 1);
    }
    __syncthreads();
    CLUSTER_SYNC();   // barriers visible before cross-CTA arrivals / multicast commits
    uint32_t tmem;
    asm("ld.shared.b32 %0, [%1];" : "=r"(tmem) : "r"(smem_u32(&s_tmem)));

    int kmax = K;
    if (CKLIM && m0 + 256 < kmax) kmax = m0 + 256;
    int nk = (kmax + 31) >> 5;

    // cg2 f16 idesc: dtype=F32, a/b=BF16, N=256, M=256
    const uint32_t IDESC = (1u << 4) | (1u << 7) | (1u << 10) | (32u << 17) | (16u << 24);

    if (wid == 0 && elect1()) {
        // this CTA's slices: +rank*4096 elems (8KB) inside each 16KB block
        long long abase = (((long long)(m0 >> 8) * kca) << 13) + (long long)rank * 4096;
        long long bbase = ((((long long)(n0 >> 8) * kcb) + kcOffB) << 13) + (long long)rank * 4096;

        auto load_chunk = [&](int c) {
            uint32_t stg = sbase + (uint32_t)(c % ST) * STAGE_BYTES;
            uint32_t fb  = smem_u32(&s_full[c % ST]);
            MBAR_EXPECT_TX(fb, 32768u);              // this CTA's 32KB
            long long ae = abase + ((long long)c << 13);
            long long be = bbase + ((long long)c << 13);
            BULK(stg,          Ah + ae, 8192u, fb);
            BULK(stg + 8192u,  Al + ae, 8192u, fb);
            BULK(stg + 16384u, Bh + be, 8192u, fb);
            BULK(stg + 24576u, Bl + be, 8192u, fb);
        };

        if (rank == 0) {
            // leader: load own slices, wait count-2 full (own tx + follower arrive), MMA
            for (int s = 0; s < ST - 1 && s < nk; s++) load_chunk(s);
            for (int kt = 0; kt < nk; kt++) {
                int c = kt + ST - 1;
                if (c < nk) {
                    if (c >= ST)
                        MBWAIT(smem_u32(&s_done[c % ST]), ((c / ST) - 1) & 1);
                    load_chunk(c);
                }
                MBWAIT(smem_u32(&s_full[kt % ST]), (kt / ST) & 1);
                uint32_t stg = sbase + (uint32_t)(kt % ST) * STAGE_BYTES;
                uint64_t dah = sdesc64(stg);
                uint64_t dal = sdesc64(stg + 8192u);
                uint64_t dbh = sdesc64(stg + 16384u);
                uint64_t dbl = sdesc64(stg + 24576u);
#pragma unroll
                for (int ks = 0; ks < 2; ks++) {
                    uint32_t en = (kt > 0 || ks > 0) ? 1u : 0u;
                    mma_bf16_cg2(tmem, dah + ks * 2, dbh + ks * 2, IDESC, en);
                    mma_bf16_cg2(tmem, dah + ks * 2, dbl + ks * 2, IDESC, 1u);
                    mma_bf16_cg2(tmem, dal + ks * 2, dbh + ks * 2, IDESC, 1u);
                }
                TC_COMMIT_MC(smem_u32(&s_done[kt % ST]), 0x3);
            }
        } else {
            // follower: load own slices, relay completion to leader's full barrier
            for (int s = 0; s < ST - 1 && s < nk; s++) load_chunk(s);
            for (int kt = 0; kt < nk; kt++) {
                int c = kt + ST - 1;
                if (c < nk) {
                    if (c >= ST)
                        MBWAIT(smem_u32(&s_done[c % ST]), ((c / ST) - 1) & 1);
                    load_chunk(c);
                }
                MBWAIT(smem_u32(&s_full[kt % ST]), (kt / ST) & 1);
                ARRIVE_RANK0(smem_u32(&s_full[kt % ST]));
            }
        }
    }

    __syncthreads();
    MBWAIT(smem_u32(&s_done[(nk - 1) % ST]), ((nk - 1) / ST) & 1);
    TC_FENCE_AFTER();

    // epilogue: this CTA's TMEM holds its 128 rows x 256 cols fp32
    {
        int gm = m0 + (int)rank * 128 + (wid & 3) * 32 + lid;
#pragma unroll
        for (int h = 0; h < 2; h++) {
            int cc = (wid >> 2) * 64 + h * 32;
            uint32_t r[32];
            LDTM_X32(r, tmem + cc);
            TC_WAIT_LD();
            if (gm < M) {
                int gout = gm;
                bool rowok = true;
                if (BATCHROW) {
                    int l = gm & (LP - 1);
                    if (l >= LL) rowok = false;
                    gout = (gm >> 10) * LL + l;
                }
                if (rowok) {
#pragma unroll
                    for (int c = 0; c < 32; c += 4) {
                        int gn = n0 + cc + c;
                        if (gn + 4 <= Nn) {
                            float v0 = __uint_as_float(r[c + 0]);
                            float v1 = __uint_as_float(r[c + 1]);
                            float v2 = __uint_as_float(r[c + 2]);
                            float v3 = __uint_as_float(r[c + 3]);
                            if (BIAS) {
                                v0 += bias[gn + 0]; v1 += bias[gn + 1];
                                v2 += bias[gn + 2]; v3 += bias[gn + 3];
                            }
                            if (SPLITOUT) {
                                bf16 h0, l0, h1, l1, h2, l2, h3, l3;
                                bsplit(v0, h0, l0); bsplit(v1, h1, l1);
                                bsplit(v2, h2, l2); bsplit(v3, h3, l3);
                                long long o = toff(gm, gn, ldc);
                                *(bf162*)(Ch + o)     = bf162(h0, h1);
                                *(bf162*)(Ch + o + 2) = bf162(h2, h3);
                                *(bf162*)(Cl + o)     = bf162(l0, l1);
                                *(bf162*)(Cl + o + 2) = bf162(l2, l3);
                            } else {
                                float4 v = make_float4(v0, v1, v2, v3);
                                *(float4*)(C + (long long)gout * ldc + gn) = v;
                            }
                        }
                    }
                }
            }
        }
    }

    __syncthreads();
    CLUSTER_SYNC();   // all cross-CTA arrivals consumed before inval/dealloc
    if (tid < ST) { MBAR_INVAL(smem_u32(&s_full[tid])); MBAR_INVAL(smem_u32(&s_done[tid])); }
    __syncthreads();
    if (wid == 0) TC_DEALLOC_CG2(tmem, 256);
    CLUSTER_SYNC();
#endif // TC_OK
}

// ================= FFMA fallback GEMM (plain sm_103 pass only; tiled reads) =================
template<bool CSKIP, bool CKLIM, bool BIAS, bool SPLITOUT, bool BATCHROW, bool DUAL>
__global__ __launch_bounds__(256, 2)
void ffgemm(const bf16* __restrict__ Ah, const bf16* __restrict__ Al,
            const bf16* __restrict__ A2h, const bf16* __restrict__ A2l,
            const bf16* __restrict__ Bh, const bf16* __restrict__ Bl,
            float* __restrict__ C, bf16* __restrict__ Ch, bf16* __restrict__ Cl,
            const float* __restrict__ bias,
            int M, int Nn, int K, int kca, int kca2, int kcb, int ldc, int kcOffB,
            long long sA, long long sA2, long long sB, long long sC)
{
#ifndef TC_OK
    const int BM = 128, BN = 128, BK = 16;
    __shared__ float As[BK][BM];
    __shared__ float Bs[BK][BN];

    long long bz = blockIdx.z;
    if (DUAL && bz >= NB) {
        Ah = A2h + (bz - NB) * sA2;
        Al = A2l + (bz - NB) * sA2;
        kca = kca2;
    } else {
        Ah += bz * sA; Al += bz * sA;
    }
    long long bzb = bz % NB;
    Bh += bzb * sB; Bl += bzb * sB;
    C += bz * sC; Ch += bz * sC; Cl += bz * sC;

    int m0 = blockIdx.y * BM;
    int n0 = blockIdx.x * BN;
    if (CSKIP && n0 > m0 + BM - 1) return;

    int tid  = threadIdx.x;
    int trow = tid >> 4;
    int tcol = tid & 15;

    float acc[8][8];
#pragma unroll
    for (int i = 0; i < 8; i++)
#pragma unroll
        for (int j = 0; j < 8; j++) acc[i][j] = 0.f;

    int ktiles = (K + BK - 1) / BK;
    if (CKLIM) {
        int kl = (m0 + BM + BK - 1) / BK;
        if (kl < ktiles) ktiles = kl;
    }

    for (int kt = 0; kt < ktiles; kt++) {
        int k0 = kt * BK;
        for (int i = tid; i < BM * BK; i += 256) {
            int r = i / BK, c = i % BK;
            float v = 0.f;
            int gr = m0 + r, gk = k0 + c;
            if (gr < M && gk < K) {
                long long e = toff(gr, gk, kca);
                v = __bfloat162float(Ah[e]) + __bfloat162float(Al[e]);
            }
            As[c][r] = v;
        }
        for (int i = tid; i < BN * BK; i += 256) {
            int r = i / BK, c = i % BK;
            float v = 0.f;
            int gr = n0 + r, gk = k0 + c;
            if (gr < Nn && gk < K) {
                long long e = toff(gr, gk + kcOffB * 32, kcb);
                v = __bfloat162float(Bh[e]) + __bfloat162float(Bl[e]);
            }
            Bs[c][r] = v;
        }
        __syncthreads();

#pragma unroll
        for (int kk = 0; kk < BK; kk++) {
            float a[8], b[8];
            *(float4*)&a[0] = *(const float4*)&As[kk][trow * 8];
            *(float4*)&a[4] = *(const float4*)&As[kk][trow * 8 + 4];
            *(float4*)&b[0] = *(const float4*)&Bs[kk][tcol * 8];
            *(float4*)&b[4] = *(const float4*)&Bs[kk][tcol * 8 + 4];
#pragma unroll
            for (int i = 0; i < 8; i++)
#pragma unroll
                for (int j = 0; j < 8; j++)
                    acc[i][j] += a[i] * b[j];
        }
        __syncthreads();
    }

#pragma unroll
    for (int i = 0; i < 8; i++) {
        int gm = m0 + trow * 8 + i;
        if (gm >= M) continue;
        int gout = gm;
        if (BATCHROW) {
            int l = gm & (LP - 1);
            if (l >= LL) continue;
            gout = (gm >> 10) * LL + l;
        }
#pragma unroll
        for (int j = 0; j < 8; j++) {
            int gn = n0 + tcol * 8 + j;
            if (gn >= Nn) continue;
            float v = acc[i][j];
            if (BIAS) v += bias[gn];
            if (SPLITOUT) {
                bf16 h, l;
                bsplit(v, h, l);
                long long e = toff(gm, gn, ldc);
                Ch[e] = h;
                Cl[e] = l;
            } else {
                C[(long long)gout * ldc + gn] = v;
            }
        }
    }
#endif // !TC_OK
}

// ---------------- positional encoding + input add (tiled split output, zero-padded) ----------------
__global__ void build_x_kernel(const float* __restrict__ inp,
                               const float* __restrict__ inp2)
{
    int idx = blockIdx.x * blockDim.x + threadIdx.x;   // over LP*DD
    if (idx >= LP * DD) return;
    int l = idx / DD;
    int j = idx % DD;
    float pe = 0.f;
    if (l < LL) {
        float rate = expf(-(float)j * 8.99447363e-3f);
        float ang  = (float)l * rate;
        pe = (j & 1) ? cosf(ang) : sinf(ang);
    }
#pragma unroll
    for (int n = 0; n < NB; n++) {
        long long e = (long long)n * LP * DD + toff(l, j, 32);
        if (l < LL) {
            long long src = ((long long)n * LL + l) * DD + j;
            bf16 h, lo;
            bsplit(inp[src] + pe, h, lo);
            g_xh[e] = h; g_xl[e] = lo;
            bsplit(inp2[src] + pe, h, lo);
            g_xuh[e] = h; g_xul[e] = lo;
        } else {
            bf16 z = __float2bfloat16_rn(0.f);
            g_xh[e] = z; g_xl[e] = z; g_xuh[e] = z; g_xul[e] = z;
        }
    }
}

// ---------------- weight split (tiled) ----------------
__global__ void wsplit5_kernel(const float* __restrict__ w0, const float* __restrict__ w1,
                               const float* __restrict__ w2, const float* __restrict__ w3,
                               const float* __restrict__ w4)
{
    int i = blockIdx.x * blockDim.x + threadIdx.x;
    int which = blockIdx.y;
    if (i >= DD * DD) return;
    const float* src = which == 0 ? w0 : which == 1 ? w1 : which == 2 ? w2 : which == 3 ? w3 : w4;
    long long e = (long long)which * DD * DD + toff(i >> 10, i & 1023, 32);
    bf16 h, l;
    bsplit(src[i], h, l);
    g_wh[e] = h; g_wl[e] = l;
}

// ---------------- fused dual causal softmax -> tiled bf16 P planes ----------------
__global__ void softmax_dual_kernel(const float* __restrict__ S,
                                    bf16* __restrict__ Ph, bf16* __restrict__ Pl)
{
    const long long zP = (long long)LP * LP;
    int q = blockIdx.x;
    int n = blockIdx.y;
    const float* r1 = S + ((long long)n * LP + q) * LL;
    const float* r2 = S + ((long long)(NB + n) * LP + q) * LL;
    int len = q + 1;
    int tid = threadIdx.x;
    __shared__ float2 red[256];

    float v1[4], v2[4];
    float mx1 = -3.4e38f, mx2 = -3.4e38f;
#pragma unroll
    for (int i = 0; i < 4; i++) {
        int k = tid + i * 256;
        if (k < len) {
            v1[i] = r1[k]; v2[i] = r2[k];
            mx1 = fmaxf(mx1, v1[i]); mx2 = fmaxf(mx2, v2[i]);
        } else { v1[i] = -3.4e38f; v2[i] = -3.4e38f; }
    }
    red[tid] = make_float2(mx1, mx2);
    __syncthreads();
    for (int s = 128; s > 0; s >>= 1) {
        if (tid < s) {
            red[tid].x = fmaxf(red[tid].x, red[tid + s].x);
            red[tid].y = fmaxf(red[tid].y, red[tid + s].y);
        }
        __syncthreads();
    }
    mx1 = red[0].x; mx2 = red[0].y;
    __syncthreads();

    float s1 = 0.f, s2 = 0.f;
#pragma unroll
    for (int i = 0; i < 4; i++) {
        int k = tid + i * 256;
        if (k < len) {
            v1[i] = expf(v1[i] - mx1); s1 += v1[i];
            v2[i] = expf(v2[i] - mx2); s2 += v2[i];
        } else { v1[i] = 0.f; v2[i] = 0.f; }
    }
    red[tid] = make_float2(s1, s2);
    __syncthreads();
    for (int s = 128; s > 0; s >>= 1) {
        if (tid < s) {
            red[tid].x += red[tid + s].x;
            red[tid].y += red[tid + s].y;
        }
        __syncthreads();
    }
    float i1 = 1.f / red[0].x, i2 = 1.f / red[0].y;

    bf16* p1h = Ph + (long long)n * zP;        bf16* p1l = Pl + (long long)n * zP;
    bf16* p2h = Ph + (long long)(NB + n) * zP; bf16* p2l = Pl + (long long)(NB + n) * zP;
    bf16 z = __float2bfloat16_rn(0.f);
#pragma unroll
    for (int i = 0; i < 4; i++) {
        int k = tid + i * 256;
        long long e = toff(q, k, 32);
        bf16 h, l;
        if (k < len) {
            bsplit(v1[i] * i1, h, l); p1h[e] = h; p1l[e] = l;
            bsplit(v2[i] * i2, h, l); p2h[e] = h; p2l[e] = l;
        } else {
            p1h[e] = z; p1l[e] = z; p2h[e] = z; p2l[e] = z;
        }
    }
}

// ---------------- combine + residual + layernorm -> tiled split yn ----------------
__global__ void fuse_ln_kernel(const float* __restrict__ inp,
                               const float* __restrict__ ln_g,
                               const float* __restrict__ ln_b)
{
    const long long zO = (long long)LP * DD;
    int rr = blockIdx.x;
    int n = rr / LL, l = rr % LL;
    const float* o1 = g_o + (long long)n * zO + (long long)l * DD;
    const float* o2 = g_o + (long long)(NB + n) * zO + (long long)l * DD;
    const float* xr = inp + (long long)rr * DD;
    int tid = threadIdx.x;

    __shared__ float ssum[256];
    __shared__ float ssq [256];

    float v[4];
    float s = 0.f, s2 = 0.f;
#pragma unroll
    for (int i = 0; i < 4; i++) {
        int d = tid + i * 256;
        float y = 0.5f * (o1[d] + o2[d]) + xr[d];
        v[i] = y;
        s  += y;
        s2 += y * y;
    }
    ssum[tid] = s;
    ssq [tid] = s2;
    __syncthreads();
    for (int st = 128; st > 0; st >>= 1) {
        if (tid < st) { ssum[tid] += ssum[tid + st]; ssq[tid] += ssq[tid + st]; }
        __syncthreads();
    }
    float mu  = ssum[0] * (1.f / DD);
    float var = ssq[0]  * (1.f / DD) - mu * mu;
    float inv = rsqrtf(var + 1e-5f);
    long long base = (long long)n * LP * DD;
#pragma unroll
    for (int i = 0; i < 4; i++) {
        int d = tid + i * 256;
        float y = (v[i] - mu) * inv * ln_g[d] + ln_b[d];
        bf16 h, l2;
        bsplit(y, h, l2);
        long long e = base + toff(l, d, 32);
        g_ynh[e] = h;
        g_ynl[e] = l2;
    }
}

// ---------------- host launch ----------------
static bool tc_live() {
    cudaFuncAttributes a{};
    cudaError_t e = cudaFuncGetAttributes(&a,
        (const void*)tgemm<false, false, false, true, false, false>);
    return e == cudaSuccess && a.numRegs > 40;
}

#define GB(T1, T2, T3, T4, T5, T6, gt, gf, Ah_, Al_, A2h_, A2l_, Bh_, Bl_, C_, Ch_, Cl_, bias_, M_, N_, K_, kca_, kca2_, kcb_, ldc_, kob_, sA_, sA2_, sB_, sC_) \
    do { \
        tgemm<T1, T2, T3, T4, T5, T6><<<gt, NTHR, SMEM_DYN>>>(Ah_, Al_, A2h_, A2l_, Bh_, Bl_, C_, Ch_, Cl_, bias_, M_, N_, K_, kca_, kca2_, kcb_, ldc_, kob_, sA_, sA2_, sB_, sC_); \
        if (!use_tc) \
            ffgemm<T1, T2, T3, T4, T5, T6><<<gf, 256>>>(Ah_, Al_, A2h_, A2l_, Bh_, Bl_, C_, Ch_, Cl_, bias_, M_, N_, K_, kca_, kca2_, kcb_, ldc_, kob_, sA_, sA2_, sB_, sC_); \
    } while (0)

extern "C" void kernel_launch(void* const* d_in, const int* in_sizes, int n_in,
                              void* d_out, int out_size)
{
    const float* inputs  = (const float*)d_in[0];
    const float* inputs2 = (const float*)d_in[1];
    const float* Wq      = (const float*)d_in[2];
    const float* Wqu     = (const float*)d_in[3];
    const float* Wk      = (const float*)d_in[4];
    const float* Wv      = (const float*)d_in[5];
    // d_in[6] W_d, d_in[7] h_vec: dead code (A == 0.5 exactly in the reference)
    const float* fc_w    = (const float*)d_in[8];
    const float* fc_b    = (const float*)d_in[9];
    const float* ln_g    = (const float*)d_in[10];
    const float* ln_b    = (const float*)d_in[11];
    float* out = (float*)d_out;

    const bool use_tc = tc_live();

    bf16 *xh, *xl, *xuh, *xul, *qkh, *qkl, *quhh, *quhl;
    bf16 *vth, *vtl, *ph, *pl, *ynh, *ynl, *wh, *wl;
    float *s, *o;
    cudaGetSymbolAddress((void**)&xh,   g_xh);
    cudaGetSymbolAddress((void**)&xl,   g_xl);
    cudaGetSymbolAddress((void**)&xuh,  g_xuh);
    cudaGetSymbolAddress((void**)&xul,  g_xul);
    cudaGetSymbolAddress((void**)&qkh,  g_qkh);
    cudaGetSymbolAddress((void**)&qkl,  g_qkl);
    cudaGetSymbolAddress((void**)&quhh, g_quhh);
    cudaGetSymbolAddress((void**)&quhl, g_quhl);
    cudaGetSymbolAddress((void**)&vth,  g_vth);
    cudaGetSymbolAddress((void**)&vtl,  g_vtl);
    cudaGetSymbolAddress((void**)&s,    g_s);
    cudaGetSymbolAddress((void**)&ph,   g_ph);
    cudaGetSymbolAddress((void**)&pl,   g_pl);
    cudaGetSymbolAddress((void**)&o,    g_o);
    cudaGetSymbolAddress((void**)&ynh,  g_ynh);
    cudaGetSymbolAddress((void**)&ynl,  g_ynl);
    cudaGetSymbolAddress((void**)&wh,   g_wh);
    cudaGetSymbolAddress((void**)&wl,   g_wl);

    cudaFuncSetAttribute(tgemm<false, false, false, true,  false, false>, cudaFuncAttributeMaxDynamicSharedMemorySize, SMEM_DYN);
    cudaFuncSetAttribute(tgemm<true,  false, false, false, false, true >, cudaFuncAttributeMaxDynamicSharedMemorySize, SMEM_DYN);
    cudaFuncSetAttribute(tgemm<false, true,  false, false, false, false>, cudaFuncAttributeMaxDynamicSharedMemorySize, SMEM_DYN);
    cudaFuncSetAttribute(tgemm<false, false, true,  false, true,  false>, cudaFuncAttributeMaxDynamicSharedMemorySize, SMEM_DYN);

    const long long sX  = (long long)LP * DD;
    const long long sQK = (long long)LP * 2 * DD;
    const long long sS  = (long long)LP * LL;
    const long long sP  = (long long)LP * LP;
    const long long sO  = (long long)LP * DD;

    bf16* wqh = wh;                       bf16* wql = wl;
    bf16* wuh = wh + 2LL * DD * DD;       bf16* wul = wl + 2LL * DD * DD;
    bf16* wvh = wh + 3LL * DD * DD;       bf16* wvl = wl + 3LL * DD * DD;
    bf16* fch = wh + 4LL * DD * DD;       bf16* fcl = wl + 4LL * DD * DD;

    const bf16* nbf = nullptr;

    // 0. split weights (tiled)
    {
        dim3 g((DD * DD + 255) / 256, 5);
        wsplit5_kernel<<<g, 256>>>(Wq, Wk, Wqu, Wv, fc_w);
    }

    // 1. x / xu (tiled, padded)
    build_x_kernel<<<(LP * DD + 255) / 256, 256>>>(inputs, inputs2);

    // cg2 grids: x = 2 * (N pair tiles of 256)
    // 2a. merged Q|K projection: [16384, 2048]
    dim3 gqkT(16, 64, 1), gqkF(16, 128, 1);
    GB(false, false, false, true, false, false, gqkT, gqkF,
       xh, xl, nbf, nbf, wqh, wql, (float*)nullptr, qkh, qkl, (const float*)nullptr,
       MP, 2 * DD, DD, 32, 0, 32, 64, 0, 0LL, 0LL, 0LL, 0LL);

    // 2b. QU projection
    dim3 gpT(8, 64, 1), gpF(8, 128, 1);
    GB(false, false, false, true, false, false, gpT, gpF,
       xuh, xul, nbf, nbf, wuh, wul, (float*)nullptr, quhh, quhl, (const float*)nullptr,
       MP, DD, DD, 32, 0, 32, 32, 0, 0LL, 0LL, 0LL, 0LL);

    // 2c. Vt = Wv @ x^T per batch
    dim3 gvT(8, 4, NB), gvF(8, 8, NB);
    GB(false, false, false, true, false, false, gvT, gvF,
       wvh, wvl, nbf, nbf, xh, xl, (float*)nullptr, vth, vtl, (const float*)nullptr,
       DD, LP, DD, 32, 0, 32, 32, 0, 0LL, 0LL, sX, sX);

    // 3. scores, BOTH streams (z = 32)
    dim3 gsT(8, 4, 2 * NB), gsF(8, 8, 2 * NB);
    GB(true, false, false, false, false, true, gsT, gsF,
       qkh, qkl, quhh, quhl, qkh, qkl, s, (bf16*)nullptr, (bf16*)nullptr, (const float*)nullptr,
       LP, LL, DD, 64, 32, 64, LL, 32, sQK, sX, sQK, sS);

    // 4. fused dual causal softmax -> tiled bf16 P planes
    dim3 gsm(LL, NB);
    softmax_dual_kernel<<<gsm, 256>>>(s, ph, pl);

    // 5. O = P @ Vt^T, BOTH streams (z = 32), CKLIM
    dim3 gvpT(8, 4, 2 * NB), gvpF(8, 8, 2 * NB);
    GB(false, true, false, false, false, false, gvpT, gvpF,
       ph, pl, nbf, nbf, vth, vtl, o, (bf16*)nullptr, (bf16*)nullptr, (const float*)nullptr,
       LP, DD, LP, 32, 0, 32, DD, 0, sP, 0LL, sX, sO);

    // 6. y = 0.5*(o1+o2) + inputs; layernorm -> tiled split yn
    fuse_ln_kernel<<<MM, 256>>>(inputs, ln_g, ln_b);

    // 7. out = yn @ fc_w^T + fc_b
    GB(false, false, true, false, true, false, gpT, gpF,
       ynh, ynl, nbf, nbf, fch, fcl, out, (bf16*)nullptr, (bf16*)nullptr, fc_b,
       MP, DD, DD, 32, 0, 32, DD, 0, 0LL, 0LL, 0LL, 0LL);
}

// round 17
// speedup vs baseline: 1.2047x; 1.2047x over previous
#include <cuda_runtime.h>
#include <cuda_bf16.h>
#include <cstdint>
#include <math.h>

#define NB 16
#define LL 1000
#define DD 1024
#define LP 1024                 // padded per-batch rows
#define MM (NB*LL)              // 16000
#define MP (NB*LP)              // 16384 padded

typedef __nv_bfloat16 bf16;
typedef __nv_bfloat162 bf162;

#if defined(__CUDA_ARCH__) && (defined(__CUDA_ARCH_FEAT_SM103_ALL) || defined(__CUDA_ARCH_FEAT_SM100_ALL))
#define TC_OK 1
#endif

// ---------------- scratch: ALL GEMM operands live in tiled-swizzled layout ----------------
// Tiled layout: blocks of 256 rows x 32 cols (16KB, SW64-swizzled, ready for MMA).
// block id = (row>>8)*KC + (col>>5).
__device__ __align__(128) bf16  g_xh  [NB*LP*DD];
__device__ __align__(128) bf16  g_xl  [NB*LP*DD];
__device__ __align__(128) bf16  g_xuh [NB*LP*DD];
__device__ __align__(128) bf16  g_xul [NB*LP*DD];
__device__ __align__(128) bf16  g_qkh [NB*LP*2*DD];
__device__ __align__(128) bf16  g_qkl [NB*LP*2*DD];
__device__ __align__(128) bf16  g_quhh[NB*LP*DD];
__device__ __align__(128) bf16  g_quhl[NB*LP*DD];
__device__ __align__(128) bf16  g_vth [NB*DD*LP];
__device__ __align__(128) bf16  g_vtl [NB*DD*LP];
__device__ float g_s   [2*NB*LP*LL];
__device__ __align__(128) bf16  g_ph  [2*NB*LP*LP];
__device__ __align__(128) bf16  g_pl  [2*NB*LP*LP];
__device__ float g_o   [2*NB*LP*DD];
__device__ __align__(128) bf16  g_ynh [NB*LP*DD];
__device__ __align__(128) bf16  g_ynl [NB*LP*DD];
__device__ __align__(128) bf16  g_wh  [5*DD*DD];
__device__ __align__(128) bf16  g_wl  [5*DD*DD];

// ================= helpers =================
__device__ __forceinline__ uint32_t smem_u32(const void* p) {
    uint32_t a;
    asm("{ .reg .u64 t; cvta.to.shared.u64 t, %1; cvt.u32.u64 %0, t; }" : "=r"(a) : "l"(p));
    return a;
}

__device__ __forceinline__ void bsplit(float v, bf16& h, bf16& l) {
    h = __float2bfloat16_rn(v);
    l = __float2bfloat16_rn(v - __bfloat162float(h));
}

#define SWZ64(o) ((o) ^ (((o) >> 3) & 0x30))

// element offset of (row, col) in a tiled buffer with KC col-chunks
__device__ __forceinline__ long long toff(int row, int col, int KC) {
    int rb = row >> 8, r = row & 255;
    int kc = col >> 5, cc = col & 31;
    long long boff = ((long long)(rb * KC + kc)) << 13;   // 8192 elems / block
    uint32_t w = SWZ64((uint32_t)(r * 64 + (cc >> 3) * 16)) + (uint32_t)(cc & 7) * 2;
    return boff + (w >> 1);
}

#ifdef TC_OK
__device__ __forceinline__ bool elect1() {
    uint32_t p;
    asm volatile("{\n\t.reg .pred p;\n\telect.sync _|p, 0xFFFFFFFF;\n\tselp.b32 %0,1,0,p;\n\t}" : "=r"(p));
    return p != 0;
}

#define TC_ALLOC(smaddr, n) \
    asm volatile("tcgen05.alloc.cta_group::1.sync.aligned.shared::cta.b32 [%0], %1;" :: "r"(smaddr), "r"(n) : "memory")
#define TC_RELINQ() \
    asm volatile("tcgen05.relinquish_alloc_permit.cta_group::1.sync.aligned;")
#define TC_DEALLOC(t, n) \
    asm volatile("tcgen05.dealloc.cta_group::1.sync.aligned.b32 %0, %1;" :: "r"(t), "r"(n))
#define TC_COMMIT(mbar) \
    asm volatile("tcgen05.commit.cta_group::1.mbarrier::arrive::one.shared::cluster.b64 [%0];" :: "r"(mbar) : "memory")
#define TC_FENCE_AFTER() \
    asm volatile("tcgen05.fence::after_thread_sync;" ::: "memory")
#define TC_WAIT_LD() \
    asm volatile("tcgen05.wait::ld.sync.aligned;" ::: "memory")
#define MBAR_INIT(a, c) \
    asm volatile("mbarrier.init.shared.b64 [%0], %1;" :: "r"(a), "r"(c) : "memory")
#define MBAR_INVAL(a) \
    asm volatile("mbarrier.inval.shared.b64 [%0];" :: "r"(a) : "memory")
#define MBAR_EXPECT_TX(a, n) \
    asm volatile("mbarrier.arrive.expect_tx.shared.b64 _, [%0], %1;" :: "r"(a), "r"(n) : "memory")
#define MBWAIT(addr, ph) do { \
    asm volatile("{\n\t.reg .pred P1;\n\tWL%=:\n\t" \
        "mbarrier.try_wait.parity.acquire.cta.shared::cta.b64 P1, [%0], %1, 0x989680;\n\t" \
        "@P1 bra.uni WD%=;\n\tbra.uni WL%=;\n\tWD%=:\n\t}" \
        :: "r"(addr), "r"(ph) : "memory"); } while (0)

#define BULK(dst, src, n, mbar) \
    asm volatile("cp.async.bulk.shared::cluster.global.mbarrier::complete_tx::bytes [%0], [%1], %2, [%3];" \
        :: "r"(dst), "l"(src), "r"(n), "r"(mbar) : "memory")

__device__ __forceinline__ void mma_bf16(uint32_t d, uint64_t ad, uint64_t bd, uint32_t idesc, uint32_t en) {
    uint32_t z = 0;
    asm volatile("{\n\t.reg .pred p;\n\tsetp.ne.u32 p, %5, 0;\n\t"
                 "tcgen05.mma.cta_group::1.kind::f16 [%0], %1, %2, %3, {%4, %4, %4, %4}, p;\n\t}"
                 :: "r"(d), "l"(ad), "l"(bd), "r"(idesc), "r"(z), "r"(en) : "memory");
}

#define LDTM_X32(r, a) \
    asm volatile("tcgen05.ld.sync.aligned.32x32b.x32.b32 " \
        "{%0, %1, %2, %3, %4, %5, %6, %7, %8, %9, %10, %11, %12, %13, %14, %15, " \
        " %16, %17, %18, %19, %20, %21, %22, %23, %24, %25, %26, %27, %28, %29, %30, %31}, [%32];" \
        : "=r"((r)[0]),  "=r"((r)[1]),  "=r"((r)[2]),  "=r"((r)[3]), \
          "=r"((r)[4]),  "=r"((r)[5]),  "=r"((r)[6]),  "=r"((r)[7]), \
          "=r"((r)[8]),  "=r"((r)[9]),  "=r"((r)[10]), "=r"((r)[11]), \
          "=r"((r)[12]), "=r"((r)[13]), "=r"((r)[14]), "=r"((r)[15]), \
          "=r"((r)[16]), "=r"((r)[17]), "=r"((r)[18]), "=r"((r)[19]), \
          "=r"((r)[20]), "=r"((r)[21]), "=r"((r)[22]), "=r"((r)[23]), \
          "=r"((r)[24]), "=r"((r)[25]), "=r"((r)[26]), "=r"((r)[27]), \
          "=r"((r)[28]), "=r"((r)[29]), "=r"((r)[30]), "=r"((r)[31]) \
        : "r"(a))

// SW64 descriptor: layout=4, version=1, SBO=32, LBO=1 (K-major, 64B rows)
__device__ __forceinline__ uint64_t sdesc64(uint32_t addr) {
    const uint64_t base = (uint64_t(4) << 61) | (uint64_t(1) << 46) |
                          (uint64_t(32) << 32) | (uint64_t(1) << 16);
    return base | ((uint64_t)(addr >> 4) & 0x3FFF);
}
#endif // TC_OK

// ================= tcgen05 bf16x2 GEMM, 256x256 tile, bulk loads, DUAL MMA ISSUERS =================
// C[M,Nn] = A[M,K] @ B[Nn,K]^T, bf16 (hi, lo) TILED operands.
// Warp 0 elect: bulk loads + half-0 MMAs; Warp 1 elect: half-1 MMAs.
// done[] barriers count=2 (one commit per issuer). ST=3 x 64KB stages.
#define ST 3
#define STAGE_BYTES 65536
#define NTHR 512
static const int SMEM_DYN = ST * STAGE_BYTES + 1024;

template<bool CSKIP, bool CKLIM, bool BIAS, bool SPLITOUT, bool BATCHROW, bool DUAL>
__global__ __launch_bounds__(NTHR, 1)
void tgemm(const bf16* __restrict__ Ah, const bf16* __restrict__ Al,
           const bf16* __restrict__ A2h, const bf16* __restrict__ A2l,
           const bf16* __restrict__ Bh, const bf16* __restrict__ Bl,
           float* __restrict__ C, bf16* __restrict__ Ch, bf16* __restrict__ Cl,
           const float* __restrict__ bias,
           int M, int Nn, int K, int kca, int kca2, int kcb, int ldc, int kcOffB,
           long long sA, long long sA2, long long sB, long long sC)
{
#ifdef TC_OK
    extern __shared__ char dsm[];
    __shared__ uint32_t s_tmem;
    __shared__ __align__(8) unsigned long long s_full[ST];
    __shared__ __align__(8) unsigned long long s_done[ST];

    int m0 = blockIdx.y * 256, n0 = blockIdx.x * 256;
    if (CSKIP && n0 > m0 + 255) return;

    long long bz = blockIdx.z;
    if (DUAL && bz >= NB) {
        Ah = A2h + (bz - NB) * sA2;
        Al = A2l + (bz - NB) * sA2;
        kca = kca2;
    } else {
        Ah += bz * sA; Al += bz * sA;
    }
    long long bzb = bz % NB;
    Bh += bzb * sB; Bl += bzb * sB;
    C += bz * sC; Ch += bz * sC; Cl += bz * sC;

    uint32_t sb_raw = smem_u32(dsm);
    uint32_t sbase  = (sb_raw + 1023u) & ~1023u;

    int tid = threadIdx.x;
    int wid = tid >> 5;
    int lid = tid & 31;

    if (wid == 0) { TC_ALLOC(smem_u32(&s_tmem), 512); TC_RELINQ(); }
    if (tid < ST) {
        MBAR_INIT(smem_u32(&s_full[tid]), 1);
        MBAR_INIT(smem_u32(&s_done[tid]), 2);     // one commit per issuer thread
    }
    __syncthreads();
    uint32_t tmem;
    asm("ld.shared.b32 %0, [%1];" : "=r"(tmem) : "r"(smem_u32(&s_tmem)));

    int kmax = K;
    if (CKLIM && m0 + 256 < kmax) kmax = m0 + 256;
    int nk = (kmax + 31) >> 5;

    const uint32_t IDESC = (1u << 4) | (1u << 7) | (1u << 10) | (32u << 17) | (8u << 24);

    if (wid == 0 && elect1()) {
        // ---- issuer 0: bulk loads + half-0 MMAs ----
        long long abase = ((long long)(m0 >> 8) * kca) << 13;
        long long bbase = (((long long)(n0 >> 8) * kcb) + kcOffB) << 13;

        auto load_chunk = [&](int c) {
            uint32_t stg = sbase + (uint32_t)(c % ST) * STAGE_BYTES;
            uint32_t fb  = smem_u32(&s_full[c % ST]);
            MBAR_EXPECT_TX(fb, 65536u);
            long long ae = abase + ((long long)c << 13);
            long long be = bbase + ((long long)c << 13);
            BULK(stg,          Ah + ae, 16384u, fb);
            BULK(stg + 16384u, Al + ae, 16384u, fb);
            BULK(stg + 32768u, Bh + be, 16384u, fb);
            BULK(stg + 49152u, Bl + be, 16384u, fb);
        };

        for (int s = 0; s < ST - 1 && s < nk; s++) load_chunk(s);

        for (int kt = 0; kt < nk; kt++) {
            int c = kt + ST - 1;
            if (c < nk) {
                if (c >= ST)
                    MBWAIT(smem_u32(&s_done[c % ST]), ((c / ST) - 1) & 1);
                load_chunk(c);
            }
            MBWAIT(smem_u32(&s_full[kt % ST]), (kt / ST) & 1);
            uint32_t stg = sbase + (uint32_t)(kt % ST) * STAGE_BYTES;
            uint64_t dah0 = sdesc64(stg);
            uint64_t dal0 = sdesc64(stg + 16384u);
            uint64_t dbh  = sdesc64(stg + 32768u);
            uint64_t dbl  = sdesc64(stg + 49152u);
#pragma unroll
            for (int ks = 0; ks < 2; ks++) {
                uint32_t en = (kt > 0 || ks > 0) ? 1u : 0u;
                mma_bf16(tmem, dah0 + ks * 2, dbh + ks * 2, IDESC, en);
                mma_bf16(tmem, dah0 + ks * 2, dbl + ks * 2, IDESC, 1u);
                mma_bf16(tmem, dal0 + ks * 2, dbh + ks * 2, IDESC, 1u);
            }
            TC_COMMIT(smem_u32(&s_done[kt % ST]));
        }
    } else if (wid == 1 && elect1()) {
        // ---- issuer 1: half-1 MMAs (rows m0+128..m0+255 -> TMEM cols 256..511) ----
        for (int kt = 0; kt < nk; kt++) {
            MBWAIT(smem_u32(&s_full[kt % ST]), (kt / ST) & 1);
            uint32_t stg = sbase + (uint32_t)(kt % ST) * STAGE_BYTES;
            uint64_t dah1 = sdesc64(stg + 8192u);
            uint64_t dal1 = sdesc64(stg + 24576u);
            uint64_t dbh  = sdesc64(stg + 32768u);
            uint64_t dbl  = sdesc64(stg + 49152u);
#pragma unroll
            for (int ks = 0; ks < 2; ks++) {
                uint32_t en = (kt > 0 || ks > 0) ? 1u : 0u;
                mma_bf16(tmem + 256, dah1 + ks * 2, dbh + ks * 2, IDESC, en);
                mma_bf16(tmem + 256, dah1 + ks * 2, dbl + ks * 2, IDESC, 1u);
                mma_bf16(tmem + 256, dal1 + ks * 2, dbh + ks * 2, IDESC, 1u);
            }
            TC_COMMIT(smem_u32(&s_done[kt % ST]));
        }
    }

    __syncthreads();
    MBWAIT(smem_u32(&s_done[(nk - 1) % ST]), ((nk - 1) / ST) & 1);
    TC_FENCE_AFTER();

    // epilogue: 16 warps x 2 halves
#pragma unroll
    for (int half = 0; half < 2; half++) {
        int gm = m0 + half * 128 + (wid & 3) * 32 + lid;
        uint32_t tb = tmem + half * 256;
#pragma unroll
        for (int h = 0; h < 2; h++) {
            int cc = (wid >> 2) * 64 + h * 32;
            uint32_t r[32];
            LDTM_X32(r, tb + cc);
            TC_WAIT_LD();
            if (gm < M) {
                int gout = gm;
                bool rowok = true;
                if (BATCHROW) {
                    int l = gm & (LP - 1);
                    if (l >= LL) rowok = false;
                    gout = (gm >> 10) * LL + l;
                }
                if (rowok) {
#pragma unroll
                    for (int c = 0; c < 32; c += 4) {
                        int gn = n0 + cc + c;
                        if (gn + 4 <= Nn) {
                            float v0 = __uint_as_float(r[c + 0]);
                            float v1 = __uint_as_float(r[c + 1]);
                            float v2 = __uint_as_float(r[c + 2]);
                            float v3 = __uint_as_float(r[c + 3]);
                            if (BIAS) {
                                v0 += bias[gn + 0]; v1 += bias[gn + 1];
                                v2 += bias[gn + 2]; v3 += bias[gn + 3];
                            }
                            if (SPLITOUT) {
                                bf16 h0, l0, h1, l1, h2, l2, h3, l3;
                                bsplit(v0, h0, l0); bsplit(v1, h1, l1);
                                bsplit(v2, h2, l2); bsplit(v3, h3, l3);
                                long long o = toff(gm, gn, ldc);
                                *(bf162*)(Ch + o)     = bf162(h0, h1);
                                *(bf162*)(Ch + o + 2) = bf162(h2, h3);
                                *(bf162*)(Cl + o)     = bf162(l0, l1);
                                *(bf162*)(Cl + o + 2) = bf162(l2, l3);
                            } else {
                                float4 v = make_float4(v0, v1, v2, v3);
                                *(float4*)(C + (long long)gout * ldc + gn) = v;
                            }
                        }
                    }
                }
            }
        }
    }

    __syncthreads();
    if (tid < ST) { MBAR_INVAL(smem_u32(&s_full[tid])); MBAR_INVAL(smem_u32(&s_done[tid])); }
    if (wid == 0) TC_DEALLOC(tmem, 512);
#endif // TC_OK
}

// ================= FFMA fallback GEMM (plain sm_103 pass only; tiled reads) =================
template<bool CSKIP, bool CKLIM, bool BIAS, bool SPLITOUT, bool BATCHROW, bool DUAL>
__global__ __launch_bounds__(256, 2)
void ffgemm(const bf16* __restrict__ Ah, const bf16* __restrict__ Al,
            const bf16* __restrict__ A2h, const bf16* __restrict__ A2l,
            const bf16* __restrict__ Bh, const bf16* __restrict__ Bl,
            float* __restrict__ C, bf16* __restrict__ Ch, bf16* __restrict__ Cl,
            const float* __restrict__ bias,
            int M, int Nn, int K, int kca, int kca2, int kcb, int ldc, int kcOffB,
            long long sA, long long sA2, long long sB, long long sC)
{
#ifndef TC_OK
    const int BM = 128, BN = 128, BK = 16;
    __shared__ float As[BK][BM];
    __shared__ float Bs[BK][BN];

    long long bz = blockIdx.z;
    if (DUAL && bz >= NB) {
        Ah = A2h + (bz - NB) * sA2;
        Al = A2l + (bz - NB) * sA2;
        kca = kca2;
    } else {
        Ah += bz * sA; Al += bz * sA;
    }
    long long bzb = bz % NB;
    Bh += bzb * sB; Bl += bzb * sB;
    C += bz * sC; Ch += bz * sC; Cl += bz * sC;

    int m0 = blockIdx.y * BM;
    int n0 = blockIdx.x * BN;
    if (CSKIP && n0 > m0 + BM - 1) return;

    int tid  = threadIdx.x;
    int trow = tid >> 4;
    int tcol = tid & 15;

    float acc[8][8];
#pragma unroll
    for (int i = 0; i < 8; i++)
#pragma unroll
        for (int j = 0; j < 8; j++) acc[i][j] = 0.f;

    int ktiles = (K + BK - 1) / BK;
    if (CKLIM) {
        int kl = (m0 + BM + BK - 1) / BK;
        if (kl < ktiles) ktiles = kl;
    }

    for (int kt = 0; kt < ktiles; kt++) {
        int k0 = kt * BK;
        for (int i = tid; i < BM * BK; i += 256) {
            int r = i / BK, c = i % BK;
            float v = 0.f;
            int gr = m0 + r, gk = k0 + c;
            if (gr < M && gk < K) {
                long long e = toff(gr, gk, kca);
                v = __bfloat162float(Ah[e]) + __bfloat162float(Al[e]);
            }
            As[c][r] = v;
        }
        for (int i = tid; i < BN * BK; i += 256) {
            int r = i / BK, c = i % BK;
            float v = 0.f;
            int gr = n0 + r, gk = k0 + c;
            if (gr < Nn && gk < K) {
                long long e = toff(gr, gk + kcOffB * 32, kcb);
                v = __bfloat162float(Bh[e]) + __bfloat162float(Bl[e]);
            }
            Bs[c][r] = v;
        }
        __syncthreads();

#pragma unroll
        for (int kk = 0; kk < BK; kk++) {
            float a[8], b[8];
            *(float4*)&a[0] = *(const float4*)&As[kk][trow * 8];
            *(float4*)&a[4] = *(const float4*)&As[kk][trow * 8 + 4];
            *(float4*)&b[0] = *(const float4*)&Bs[kk][tcol * 8];
            *(float4*)&b[4] = *(const float4*)&Bs[kk][tcol * 8 + 4];
#pragma unroll
            for (int i = 0; i < 8; i++)
#pragma unroll
                for (int j = 0; j < 8; j++)
                    acc[i][j] += a[i] * b[j];
        }
        __syncthreads();
    }

#pragma unroll
    for (int i = 0; i < 8; i++) {
        int gm = m0 + trow * 8 + i;
        if (gm >= M) continue;
        int gout = gm;
        if (BATCHROW) {
            int l = gm & (LP - 1);
            if (l >= LL) continue;
            gout = (gm >> 10) * LL + l;
        }
#pragma unroll
        for (int j = 0; j < 8; j++) {
            int gn = n0 + tcol * 8 + j;
            if (gn >= Nn) continue;
            float v = acc[i][j];
            if (BIAS) v += bias[gn];
            if (SPLITOUT) {
                bf16 h, l;
                bsplit(v, h, l);
                long long e = toff(gm, gn, ldc);
                Ch[e] = h;
                Cl[e] = l;
            } else {
                C[(long long)gout * ldc + gn] = v;
            }
        }
    }
#endif // !TC_OK
}

// ---------------- positional encoding + input add (tiled split output, zero-padded) ----------------
__global__ void build_x_kernel(const float* __restrict__ inp,
                               const float* __restrict__ inp2)
{
    int idx = blockIdx.x * blockDim.x + threadIdx.x;   // over LP*DD
    if (idx >= LP * DD) return;
    int l = idx / DD;
    int j = idx % DD;
    float pe = 0.f;
    if (l < LL) {
        float rate = expf(-(float)j * 8.99447363e-3f);
        float ang  = (float)l * rate;
        pe = (j & 1) ? cosf(ang) : sinf(ang);
    }
#pragma unroll
    for (int n = 0; n < NB; n++) {
        long long e = (long long)n * LP * DD + toff(l, j, 32);
        if (l < LL) {
            long long src = ((long long)n * LL + l) * DD + j;
            bf16 h, lo;
            bsplit(inp[src] + pe, h, lo);
            g_xh[e] = h; g_xl[e] = lo;
            bsplit(inp2[src] + pe, h, lo);
            g_xuh[e] = h; g_xul[e] = lo;
        } else {
            bf16 z = __float2bfloat16_rn(0.f);
            g_xh[e] = z; g_xl[e] = z; g_xuh[e] = z; g_xul[e] = z;
        }
    }
}

// ---------------- weight split (tiled) ----------------
__global__ void wsplit5_kernel(const float* __restrict__ w0, const float* __restrict__ w1,
                               const float* __restrict__ w2, const float* __restrict__ w3,
                               const float* __restrict__ w4)
{
    int i = blockIdx.x * blockDim.x + threadIdx.x;
    int which = blockIdx.y;
    if (i >= DD * DD) return;
    const float* src = which == 0 ? w0 : which == 1 ? w1 : which == 2 ? w2 : which == 3 ? w3 : w4;
    long long e = (long long)which * DD * DD + toff(i >> 10, i & 1023, 32);
    bf16 h, l;
    bsplit(src[i], h, l);
    g_wh[e] = h; g_wl[e] = l;
}

// ---------------- fused dual causal softmax -> tiled bf16 P planes ----------------
__global__ void softmax_dual_kernel(const float* __restrict__ S,
                                    bf16* __restrict__ Ph, bf16* __restrict__ Pl)
{
    const long long zP = (long long)LP * LP;
    int q = blockIdx.x;
    int n = blockIdx.y;
    const float* r1 = S + ((long long)n * LP + q) * LL;
    const float* r2 = S + ((long long)(NB + n) * LP + q) * LL;
    int len = q + 1;
    int tid = threadIdx.x;
    __shared__ float2 red[256];

    float v1[4], v2[4];
    float mx1 = -3.4e38f, mx2 = -3.4e38f;
#pragma unroll
    for (int i = 0; i < 4; i++) {
        int k = tid + i * 256;
        if (k < len) {
            v1[i] = r1[k]; v2[i] = r2[k];
            mx1 = fmaxf(mx1, v1[i]); mx2 = fmaxf(mx2, v2[i]);
        } else { v1[i] = -3.4e38f; v2[i] = -3.4e38f; }
    }
    red[tid] = make_float2(mx1, mx2);
    __syncthreads();
    for (int s = 128; s > 0; s >>= 1) {
        if (tid < s) {
            red[tid].x = fmaxf(red[tid].x, red[tid + s].x);
            red[tid].y = fmaxf(red[tid].y, red[tid + s].y);
        }
        __syncthreads();
    }
    mx1 = red[0].x; mx2 = red[0].y;
    __syncthreads();

    float s1 = 0.f, s2 = 0.f;
#pragma unroll
    for (int i = 0; i < 4; i++) {
        int k = tid + i * 256;
        if (k < len) {
            v1[i] = expf(v1[i] - mx1); s1 += v1[i];
            v2[i] = expf(v2[i] - mx2); s2 += v2[i];
        } else { v1[i] = 0.f; v2[i] = 0.f; }
    }
    red[tid] = make_float2(s1, s2);
    __syncthreads();
    for (int s = 128; s > 0; s >>= 1) {
        if (tid < s) {
            red[tid].x += red[tid + s].x;
            red[tid].y += red[tid + s].y;
        }
        __syncthreads();
    }
    float i1 = 1.f / red[0].x, i2 = 1.f / red[0].y;

    bf16* p1h = Ph + (long long)n * zP;        bf16* p1l = Pl + (long long)n * zP;
    bf16* p2h = Ph + (long long)(NB + n) * zP; bf16* p2l = Pl + (long long)(NB + n) * zP;
    bf16 z = __float2bfloat16_rn(0.f);
#pragma unroll
    for (int i = 0; i < 4; i++) {
        int k = tid + i * 256;
        long long e = toff(q, k, 32);
        bf16 h, l;
        if (k < len) {
            bsplit(v1[i] * i1, h, l); p1h[e] = h; p1l[e] = l;
            bsplit(v2[i] * i2, h, l); p2h[e] = h; p2l[e] = l;
        } else {
            p1h[e] = z; p1l[e] = z; p2h[e] = z; p2l[e] = z;
        }
    }
}

// ---------------- combine + residual + layernorm -> tiled split yn ----------------
__global__ void fuse_ln_kernel(const float* __restrict__ inp,
                               const float* __restrict__ ln_g,
                               const float* __restrict__ ln_b)
{
    const long long zO = (long long)LP * DD;
    int rr = blockIdx.x;
    int n = rr / LL, l = rr % LL;
    const float* o1 = g_o + (long long)n * zO + (long long)l * DD;
    const float* o2 = g_o + (long long)(NB + n) * zO + (long long)l * DD;
    const float* xr = inp + (long long)rr * DD;
    int tid = threadIdx.x;

    __shared__ float ssum[256];
    __shared__ float ssq [256];

    float v[4];
    float s = 0.f, s2 = 0.f;
#pragma unroll
    for (int i = 0; i < 4; i++) {
        int d = tid + i * 256;
        float y = 0.5f * (o1[d] + o2[d]) + xr[d];
        v[i] = y;
        s  += y;
        s2 += y * y;
    }
    ssum[tid] = s;
    ssq [tid] = s2;
    __syncthreads();
    for (int st = 128; st > 0; st >>= 1) {
        if (tid < st) { ssum[tid] += ssum[tid + st]; ssq[tid] += ssq[tid + st]; }
        __syncthreads();
    }
    float mu  = ssum[0] * (1.f / DD);
    float var = ssq[0]  * (1.f / DD) - mu * mu;
    float inv = rsqrtf(var + 1e-5f);
    long long base = (long long)n * LP * DD;
#pragma unroll
    for (int i = 0; i < 4; i++) {
        int d = tid + i * 256;
        float y = (v[i] - mu) * inv * ln_g[d] + ln_b[d];
        bf16 h, l2;
        bsplit(y, h, l2);
        long long e = base + toff(l, d, 32);
        g_ynh[e] = h;
        g_ynl[e] = l2;
    }
}

// ---------------- host launch ----------------
static bool tc_live() {
    cudaFuncAttributes a{};
    cudaError_t e = cudaFuncGetAttributes(&a,
        (const void*)tgemm<false, false, false, true, false, false>);
    return e == cudaSuccess && a.numRegs > 40;
}

#define GB(T1, T2, T3, T4, T5, T6, gt, gf, Ah_, Al_, A2h_, A2l_, Bh_, Bl_, C_, Ch_, Cl_, bias_, M_, N_, K_, kca_, kca2_, kcb_, ldc_, kob_, sA_, sA2_, sB_, sC_) \
    do { \
        tgemm<T1, T2, T3, T4, T5, T6><<<gt, NTHR, SMEM_DYN>>>(Ah_, Al_, A2h_, A2l_, Bh_, Bl_, C_, Ch_, Cl_, bias_, M_, N_, K_, kca_, kca2_, kcb_, ldc_, kob_, sA_, sA2_, sB_, sC_); \
        if (!use_tc) \
            ffgemm<T1, T2, T3, T4, T5, T6><<<gf, 256>>>(Ah_, Al_, A2h_, A2l_, Bh_, Bl_, C_, Ch_, Cl_, bias_, M_, N_, K_, kca_, kca2_, kcb_, ldc_, kob_, sA_, sA2_, sB_, sC_); \
    } while (0)

extern "C" void kernel_launch(void* const* d_in, const int* in_sizes, int n_in,
                              void* d_out, int out_size)
{
    const float* inputs  = (const float*)d_in[0];
    const float* inputs2 = (const float*)d_in[1];
    const float* Wq      = (const float*)d_in[2];
    const float* Wqu     = (const float*)d_in[3];
    const float* Wk      = (const float*)d_in[4];
    const float* Wv      = (const float*)d_in[5];
    // d_in[6] W_d, d_in[7] h_vec: dead code (A == 0.5 exactly in the reference)
    const float* fc_w    = (const float*)d_in[8];
    const float* fc_b    = (const float*)d_in[9];
    const float* ln_g    = (const float*)d_in[10];
    const float* ln_b    = (const float*)d_in[11];
    float* out = (float*)d_out;

    const bool use_tc = tc_live();

    bf16 *xh, *xl, *xuh, *xul, *qkh, *qkl, *quhh, *quhl;
    bf16 *vth, *vtl, *ph, *pl, *ynh, *ynl, *wh, *wl;
    float *s, *o;
    cudaGetSymbolAddress((void**)&xh,   g_xh);
    cudaGetSymbolAddress((void**)&xl,   g_xl);
    cudaGetSymbolAddress((void**)&xuh,  g_xuh);
    cudaGetSymbolAddress((void**)&xul,  g_xul);
    cudaGetSymbolAddress((void**)&qkh,  g_qkh);
    cudaGetSymbolAddress((void**)&qkl,  g_qkl);
    cudaGetSymbolAddress((void**)&quhh, g_quhh);
    cudaGetSymbolAddress((void**)&quhl, g_quhl);
    cudaGetSymbolAddress((void**)&vth,  g_vth);
    cudaGetSymbolAddress((void**)&vtl,  g_vtl);
    cudaGetSymbolAddress((void**)&s,    g_s);
    cudaGetSymbolAddress((void**)&ph,   g_ph);
    cudaGetSymbolAddress((void**)&pl,   g_pl);
    cudaGetSymbolAddress((void**)&o,    g_o);
    cudaGetSymbolAddress((void**)&ynh,  g_ynh);
    cudaGetSymbolAddress((void**)&ynl,  g_ynl);
    cudaGetSymbolAddress((void**)&wh,   g_wh);
    cudaGetSymbolAddress((void**)&wl,   g_wl);

    cudaFuncSetAttribute(tgemm<false, false, false, true,  false, false>, cudaFuncAttributeMaxDynamicSharedMemorySize, SMEM_DYN);
    cudaFuncSetAttribute(tgemm<true,  false, false, false, false, true >, cudaFuncAttributeMaxDynamicSharedMemorySize, SMEM_DYN);
    cudaFuncSetAttribute(tgemm<false, true,  false, false, false, false>, cudaFuncAttributeMaxDynamicSharedMemorySize, SMEM_DYN);
    cudaFuncSetAttribute(tgemm<false, false, true,  false, true,  false>, cudaFuncAttributeMaxDynamicSharedMemorySize, SMEM_DYN);

    const long long sX  = (long long)LP * DD;
    const long long sQK = (long long)LP * 2 * DD;
    const long long sS  = (long long)LP * LL;
    const long long sP  = (long long)LP * LP;
    const long long sO  = (long long)LP * DD;

    bf16* wqh = wh;                       bf16* wql = wl;
    bf16* wuh = wh + 2LL * DD * DD;       bf16* wul = wl + 2LL * DD * DD;
    bf16* wvh = wh + 3LL * DD * DD;       bf16* wvl = wl + 3LL * DD * DD;
    bf16* fch = wh + 4LL * DD * DD;       bf16* fcl = wl + 4LL * DD * DD;

    const bf16* nbf = nullptr;

    // 0. split weights (tiled)
    {
        dim3 g((DD * DD + 255) / 256, 5);
        wsplit5_kernel<<<g, 256>>>(Wq, Wk, Wqu, Wv, fc_w);
    }

    // 1. x / xu (tiled, batch rows padded to 1024, pad rows zero)
    build_x_kernel<<<(LP * DD + 255) / 256, 256>>>(inputs, inputs2);

    // 2a. merged Q|K projection: [16384, 2048]
    dim3 gqkT(8, 64, 1), gqkF(16, 128, 1);
    GB(false, false, false, true, false, false, gqkT, gqkF,
       xh, xl, nbf, nbf, wqh, wql, (float*)nullptr, qkh, qkl, (const float*)nullptr,
       MP, 2 * DD, DD, 32, 0, 32, 64, 0, 0LL, 0LL, 0LL, 0LL);

    // 2b. QU projection
    dim3 gpT(4, 64, 1), gpF(8, 128, 1);
    GB(false, false, false, true, false, false, gpT, gpF,
       xuh, xul, nbf, nbf, wuh, wul, (float*)nullptr, quhh, quhl, (const float*)nullptr,
       MP, DD, DD, 32, 0, 32, 32, 0, 0LL, 0LL, 0LL, 0LL);

    // 2c. Vt = Wv @ x^T per batch
    dim3 gvT(4, 4, NB), gvF(8, 8, NB);
    GB(false, false, false, true, false, false, gvT, gvF,
       wvh, wvl, nbf, nbf, xh, xl, (float*)nullptr, vth, vtl, (const float*)nullptr,
       DD, LP, DD, 32, 0, 32, 32, 0, 0LL, 0LL, sX, sX);

    // 3. scores, BOTH streams (z = 32)
    dim3 gsT(4, 4, 2 * NB), gsF(8, 8, 2 * NB);
    GB(true, false, false, false, false, true, gsT, gsF,
       qkh, qkl, quhh, quhl, qkh, qkl, s, (bf16*)nullptr, (bf16*)nullptr, (const float*)nullptr,
       LP, LL, DD, 64, 32, 64, LL, 32, sQK, sX, sQK, sS);

    // 4. fused dual causal softmax -> tiled bf16 P planes
    dim3 gsm(LL, NB);
    softmax_dual_kernel<<<gsm, 256>>>(s, ph, pl);

    // 5. O = P @ Vt^T, BOTH streams (z = 32), CKLIM
    dim3 gvpT(4, 4, 2 * NB), gvpF(8, 8, 2 * NB);
    GB(false, true, false, false, false, false, gvpT, gvpF,
       ph, pl, nbf, nbf, vth, vtl, o, (bf16*)nullptr, (bf16*)nullptr, (const float*)nullptr,
       LP, DD, LP, 32, 0, 32, DD, 0, sP, 0LL, sX, sO);

    // 6. y = 0.5*(o1+o2) + inputs; layernorm -> tiled split yn
    fuse_ln_kernel<<<MM, 256>>>(inputs, ln_g, ln_b);

    // 7. out = yn @ fc_w^T + fc_b (BATCHROW remaps padded rows -> 16000-row output)
    GB(false, false, true, false, true, false, gpT, gpF,
       ynh, ynl, nbf, nbf, fch, fcl, out, (bf16*)nullptr, (bf16*)nullptr, fc_b,
       MP, DD, DD, 32, 0, 32, DD, 0, 0LL, 0LL, 0LL, 0LL);
}